// round 15
// baseline (speedup 1.0000x reference)
#include <cuda_runtime.h>

// DigitCaps dynamic routing — ONE fused kernel, per-class flag pipeline.
// B=64, R=6912, I=8, C=10, O=16, 3 iterations.
//
// Grid (144 rblocks, 10 classes), 192 threads. CTA (rblk,c):
//   phase0: p=W^T x; acc[c] += p            (144th finisher: out0[c]=squash, flag0[c])
//   wait flag0[c]
//   phase1: w=exp(p.out0); acc += w*p       (finisher: out1[c]=squash, flag1[c])
//   wait flag1[c]
//   phase2: w=exp(p.(out0+out1)); acc += w*p (finisher: dout[c]=squash, reset state)
// Per-class deps -> classes pipeline through the machine; no global convoys,
// no extra launches. W tile staged ONCE per CTA, reused by all 3 phases.
// Replay-clean: each class's phase-2 finisher resets ctr/flags/accumulators.

#define R_DIM 6912
#define B_DIM 64
#define C_DIM 10
#define R_BLK 48
#define NBLK (R_DIM / R_BLK)              // 144 CTAs per class

typedef unsigned long long u64;

// +2 r slack: depth-1 x prefetch reads one r past the block
__device__ __align__(16) float g_xT[(R_DIM + 2) * 2 * B_DIM * 4];
__device__ __align__(16) float g_acc[C_DIM * B_DIM * 16];
__device__ __align__(16) float g_accw[C_DIM * B_DIM];
__device__ __align__(16) float g_out[2][C_DIM * B_DIM * 16];
__device__ unsigned g_ctr[3][C_DIM];      // zero-init; reset each run
__device__ unsigned g_flag[2][C_DIM];

__device__ __forceinline__ u64 pack2(float lo, float hi) {
    u64 r; asm("mov.b64 %0, {%1, %2};" : "=l"(r) : "f"(lo), "f"(hi)); return r;
}
__device__ __forceinline__ void unpack2(u64 v, float& lo, float& hi) {
    asm("mov.b64 {%0, %1}, %2;" : "=f"(lo), "=f"(hi) : "l"(v));
}
__device__ __forceinline__ u64 fma2(u64 a, u64 b, u64 c) {
    u64 d; asm("fma.rn.f32x2 %0, %1, %2, %3;" : "=l"(d) : "l"(a), "l"(b), "l"(c)); return d;
}
__device__ __forceinline__ u64 add2(u64 a, u64 b) {
    u64 d; asm("add.rn.f32x2 %0, %1, %2;" : "=l"(d) : "l"(a), "l"(b)); return d;
}
__device__ __forceinline__ unsigned smem_u32(const void* p) {
    return (unsigned)__cvta_generic_to_shared(p);
}
__device__ __forceinline__ void cp_async16(unsigned saddr, const void* g) {
    asm volatile("cp.async.cg.shared.global [%0], [%1], 16;" :: "r"(saddr), "l"(g));
}

// x as float4 matrix [64][13824] -> [13824][64]
__global__ void k_transpose(const float4* __restrict__ x4) {
    __shared__ float4 tile[32][33];
    const int jb = blockIdx.x * 32;
    const int bb = blockIdx.y * 32;
    const int tx = threadIdx.x, ty = threadIdx.y;   // 32 x 8
    #pragma unroll
    for (int k = 0; k < 32; k += 8)
        tile[ty + k][tx] = x4[(size_t)(bb + ty + k) * (R_DIM * 2) + jb + tx];
    __syncthreads();
    float4* out4 = reinterpret_cast<float4*>(g_xT);
    #pragma unroll
    for (int k = 0; k < 32; k += 8)
        out4[(size_t)(jb + ty + k) * B_DIM + bb + tx] = tile[tx][ty + k];
}

// One routing phase: compute + per-class atomics (R14 body, W already in sW).
template <int MODE>
__device__ __forceinline__ void run_phase(
    const int c, const int rblock, const int tid,
    const float* sW, float (*sredP)[B_DIM][16], float (*sredW)[B_DIM])
{
    const int warp   = tid >> 5;
    const int lane   = tid & 31;
    const int rgroup = warp >> 1;
    const int bhalf  = warp & 1;
    const int oh     = lane >> 4;
    const int bq     = lane & 15;
    const int b0     = bhalf * 32 + bq;
    const int b1     = b0 + 16;

    u64 ov0[4], ov1[4];
    if (MODE != 0) {
        const u64* p00 = reinterpret_cast<const u64*>(g_out[0] + (c * B_DIM + b0) * 16 + oh * 8);
        const u64* p01 = reinterpret_cast<const u64*>(g_out[0] + (c * B_DIM + b1) * 16 + oh * 8);
        #pragma unroll
        for (int t = 0; t < 4; t++) { ov0[t] = p00[t]; ov1[t] = p01[t]; }
        if (MODE == 2) {
            const u64* p10 = reinterpret_cast<const u64*>(g_out[1] + (c * B_DIM + b0) * 16 + oh * 8);
            const u64* p11 = reinterpret_cast<const u64*>(g_out[1] + (c * B_DIM + b1) * 16 + oh * 8);
            #pragma unroll
            for (int t = 0; t < 4; t++) { ov0[t] = add2(ov0[t], p10[t]); ov1[t] = add2(ov1[t], p11[t]); }
        }
    }

    u64 acc0[4], acc1[4];
    #pragma unroll
    for (int t = 0; t < 4; t++) { acc0[t] = 0ull; acc1[t] = 0ull; }
    float accw0 = 0.0f, accw1 = 0.0f;

    const float4* xb4 = reinterpret_cast<const float4*>(g_xT)
                      + (size_t)(rblock + rgroup * 16) * 2 * B_DIM;
    float4 pa0 = xb4[b0], pb0 = xb4[B_DIM + b0];
    float4 pa1 = xb4[b1], pb1 = xb4[B_DIM + b1];

    #pragma unroll 2
    for (int k = 0; k < 16; k++) {
        float4 xa0 = pa0, xb0_ = pb0, xa1 = pa1, xb1_ = pb1;
        {
            const float4* nx = xb4 + (size_t)(k + 1) * 2 * B_DIM;  // padded: safe at k=15
            pa0 = nx[b0]; pb0 = nx[B_DIM + b0];
            pa1 = nx[b1]; pb1 = nx[B_DIM + b1];
        }
        const float xf0[8] = {xa0.x, xa0.y, xa0.z, xa0.w, xb0_.x, xb0_.y, xb0_.z, xb0_.w};
        const float xf1[8] = {xa1.x, xa1.y, xa1.z, xa1.w, xb1_.x, xb1_.y, xb1_.z, xb1_.w};

        const int rl = rgroup * 16 + k;
        const ulonglong2* wp = reinterpret_cast<const ulonglong2*>(sW + rl * 128 + oh * 8);

        u64 p0[4], p1[4];
        #pragma unroll
        for (int t = 0; t < 4; t++) { p0[t] = 0ull; p1[t] = 0ull; }

        #pragma unroll
        for (int i = 0; i < 8; i++) {
            ulonglong2 wA = wp[i * 4 + 0];
            ulonglong2 wB = wp[i * 4 + 1];
            u64 xx0 = pack2(xf0[i], xf0[i]);
            u64 xx1 = pack2(xf1[i], xf1[i]);
            p0[0] = fma2(wA.x, xx0, p0[0]); p0[1] = fma2(wA.y, xx0, p0[1]);
            p0[2] = fma2(wB.x, xx0, p0[2]); p0[3] = fma2(wB.y, xx0, p0[3]);
            p1[0] = fma2(wA.x, xx1, p1[0]); p1[1] = fma2(wA.y, xx1, p1[1]);
            p1[2] = fma2(wB.x, xx1, p1[2]); p1[3] = fma2(wB.y, xx1, p1[3]);
        }

        if (MODE == 0) {
            #pragma unroll
            for (int t = 0; t < 4; t++) {
                acc0[t] = add2(acc0[t], p0[t]);
                acc1[t] = add2(acc1[t], p1[t]);
            }
        } else {
            u64 d0 = 0ull, d1 = 0ull;
            #pragma unroll
            for (int t = 0; t < 4; t++) {
                d0 = fma2(p0[t], ov0[t], d0);
                d1 = fma2(p1[t], ov1[t], d1);
            }
            float lo, hi;
            unpack2(d0, lo, hi); float del0 = lo + hi;
            unpack2(d1, lo, hi); float del1 = lo + hi;
            del0 += __shfl_xor_sync(0xffffffffu, del0, 16);
            del1 += __shfl_xor_sync(0xffffffffu, del1, 16);
            float mydel = oh ? del1 : del0;
            float myexp = __expf(fminf(mydel, 70.0f));
            float otexp = __shfl_xor_sync(0xffffffffu, myexp, 16);
            float w0 = oh ? otexp : myexp;
            float w1 = oh ? myexp : otexp;
            accw0 += w0; accw1 += w1;
            u64 w20 = pack2(w0, w0), w21 = pack2(w1, w1);
            #pragma unroll
            for (int t = 0; t < 4; t++) {
                acc0[t] = fma2(p0[t], w20, acc0[t]);
                acc1[t] = fma2(p1[t], w21, acc1[t]);
            }
        }
    }

    {
        float2* s0 = reinterpret_cast<float2*>(&sredP[rgroup][b0][oh * 8]);
        float2* s1 = reinterpret_cast<float2*>(&sredP[rgroup][b1][oh * 8]);
        #pragma unroll
        for (int t = 0; t < 4; t++) {
            float lo, hi;
            unpack2(acc0[t], lo, hi); s0[t] = make_float2(lo, hi);
            unpack2(acc1[t], lo, hi); s1[t] = make_float2(lo, hi);
        }
        if (MODE != 0 && oh == 0) { sredW[rgroup][b0] = accw0; sredW[rgroup][b1] = accw1; }
    }
    __syncthreads();

    for (int idx = tid; idx < B_DIM * 16; idx += 192) {
        const int bb = idx >> 4, o = idx & 15;
        float v = sredP[0][bb][o] + sredP[1][bb][o] + sredP[2][bb][o];
        atomicAdd(&g_acc[c * (B_DIM * 16) + idx], v);
    }
    if (MODE != 0 && tid < B_DIM) {
        float v = sredW[0][tid] + sredW[1][tid] + sredW[2][tid];
        atomicAdd(&g_accw[c * B_DIM + tid], v);
    }
    __syncthreads();   // sredP reusable by next phase
}

// Per-class squash by the finisher CTA (MODE chooses destination).
template <int MODE>
__device__ __forceinline__ void squash_class(const int c, const int tid, float* dout) {
    for (int b = tid; b < B_DIM; b += 192) {
        const int pair = c * B_DIM + b;
        const float* a = g_acc + pair * 16;
        float invw = (MODE == 0) ? (1.0f / (float)R_DIM) : (1.0f / a[16 - 16 + 0] * 0.0f + 1.0f / g_accw[pair]);
        float s[16], sq = 0.0f;
        #pragma unroll
        for (int o = 0; o < 16; o++) { s[o] = a[o] * invw; sq += s[o] * s[o]; }
        float coef = sq / ((1.0f + sq) * sqrtf(sq));
        float* dst = (MODE == 2) ? (dout + pair * 16) : (g_out[MODE] + pair * 16);
        #pragma unroll
        for (int o = 0; o < 16; o++) dst[o] = coef * s[o];
    }
    __syncthreads();
    // zero this class's accumulators for the next phase / replay
    for (int idx = tid; idx < B_DIM * 16; idx += 192) g_acc[c * (B_DIM * 16) + idx] = 0.0f;
    for (int idx = tid; idx < B_DIM; idx += 192) g_accw[c * B_DIM + idx] = 0.0f;
}

__global__ void __launch_bounds__(192, 3)
k_fused(const float* __restrict__ Wg, float* __restrict__ dout) {
    __shared__ __align__(16) float sW[R_BLK * 128];   // 24 KB, reused by all phases
    __shared__ float sredP[3][B_DIM][16];             // 12 KB
    __shared__ float sredW[3][B_DIM];
    __shared__ unsigned s_rank;

    const int c      = blockIdx.y;
    const int rblock = blockIdx.x * R_BLK;
    const int tid    = threadIdx.x;

    // stage W tile ONCE (contiguous 24 KB)
    {
        const char* src = reinterpret_cast<const char*>(Wg + ((size_t)c * R_DIM + rblock) * 128);
        unsigned dst = smem_u32(sW);
        #pragma unroll
        for (int s = 0; s < 8; s++)
            cp_async16(dst + (tid + s * 192) * 16, src + (size_t)(tid + s * 192) * 16);
        asm volatile("cp.async.commit_group;");
        asm volatile("cp.async.wait_group 0;");
    }
    __syncthreads();

    // ---------- PHASE 0 ----------
    run_phase<0>(c, rblock, tid, sW, sredP, sredW);
    __threadfence();
    if (tid == 0) s_rank = atomicAdd(&g_ctr[0][c], 1);
    __syncthreads();
    if (s_rank == NBLK - 1) {
        squash_class<0>(c, tid, dout);
        __threadfence();
        if (tid == 0) atomicExch(&g_flag[0][c], 1u);
    }
    if (tid == 0) {
        while (atomicAdd(&g_flag[0][c], 0u) == 0u) __nanosleep(128);
    }
    __syncthreads();
    __threadfence();   // acquire: order g_out[0]/g_acc reads after flag

    // ---------- PHASE 1 ----------
    run_phase<1>(c, rblock, tid, sW, sredP, sredW);
    __threadfence();
    if (tid == 0) s_rank = atomicAdd(&g_ctr[1][c], 1);
    __syncthreads();
    if (s_rank == NBLK - 1) {
        squash_class<1>(c, tid, dout);
        __threadfence();
        if (tid == 0) atomicExch(&g_flag[1][c], 1u);
    }
    if (tid == 0) {
        while (atomicAdd(&g_flag[1][c], 0u) == 0u) __nanosleep(128);
    }
    __syncthreads();
    __threadfence();

    // ---------- PHASE 2 ----------
    run_phase<2>(c, rblock, tid, sW, sredP, sredW);
    __threadfence();
    if (tid == 0) s_rank = atomicAdd(&g_ctr[2][c], 1);
    __syncthreads();
    if (s_rank == NBLK - 1) {
        squash_class<2>(c, tid, dout);
        // reset per-class state for graph replay
        __syncthreads();
        if (tid == 0) {
            g_ctr[0][c] = 0; g_ctr[1][c] = 0; g_ctr[2][c] = 0;
            g_flag[0][c] = 0; g_flag[1][c] = 0;
        }
    }
}

extern "C" void kernel_launch(void* const* d_in, const int* in_sizes, int n_in,
                              void* d_out, int out_size) {
    const float* x = (const float*)d_in[0];          // [64, 6912, 8]
    const float* W = (const float*)d_in[1];          // [10, 6912, 8, 16]
    float* out = (float*)d_out;                      // [10, 64, 1, 1, 16]

    dim3 tgrid(R_DIM * 2 / 32, B_DIM / 32);          // (432, 2)
    k_transpose<<<tgrid, dim3(32, 8)>>>(reinterpret_cast<const float4*>(x));

    dim3 grid(NBLK, C_DIM);                          // (144, 10)
    k_fused<<<grid, 192>>>(W, out);
}